// round 5
// baseline (speedup 1.0000x reference)
#include <cuda_runtime.h>
#include <cstdint>

#define ROWS_TOTAL 32768
#define DIM 768
#define NF 16
#define NQ 8
#define BLOCK 256
#define ROWS_PB 64                  /* 4 threads per row */
#define KB 32
#define LDX 36
#define NCHUNK (DIM / KB)           /* 24 */
#define W_FLOATS (DIM * NF)         /* 12288 = 48KB */
#define XS_FLOATS (ROWS_PB * LDX)   /* 2304 */
#define SMEM_BYTES ((W_FLOATS + 2 * XS_FLOATS) * 4)  /* 67584 B -> 3 blocks/SM */

__device__ __forceinline__ void ffma2(unsigned long long &d,
                                      unsigned long long a,
                                      unsigned long long b) {
    asm("fma.rn.f32x2 %0, %1, %2, %0;" : "+l"(d) : "l"(a), "l"(b));
}

__device__ __forceinline__ unsigned long long splat(float v) {
    unsigned long long r;
    asm("mov.b64 %0, {%1, %1};" : "=l"(r) : "f"(v));
    return r;
}

__device__ __forceinline__ void cp_async16(float* dst, const float* src) {
    unsigned int d = (unsigned int)__cvta_generic_to_shared(dst);
    asm volatile("cp.async.cg.shared.global [%0], [%1], 16;" :: "r"(d), "l"(src));
}

__device__ __forceinline__ void stage_x(const float* __restrict__ x,
                                        float* __restrict__ dst,
                                        int base, int ch, int tid) {
    const float* src = x + (size_t)base * DIM + ch * KB;
    // 64 rows * 32 floats = 512 float4 ; 256 threads -> 2 each
    #pragma unroll
    for (int i = 0; i < 2; i++) {
        int pos = i * BLOCK + tid;
        int row = pos >> 3, c4 = (pos & 7) << 2;
        cp_async16(dst + row * LDX + c4, src + (size_t)row * DIM + c4);
    }
    asm volatile("cp.async.commit_group;");
}

__global__ __launch_bounds__(BLOCK)
void qadapter_kernel(const float* __restrict__ x,
                     const float* __restrict__ W,
                     const float* __restrict__ b,
                     const float* __restrict__ enc,
                     float* __restrict__ out) {
    extern __shared__ float smem[];
    float* W_s = smem;                 // 12288 floats, natural row-major
    float* x_s = smem + W_FLOATS;      // 2 x 2304 floats

    const int tid = threadIdx.x;
    const int q   = tid & 3;           // k-quarter: handles k == q (mod 4)
    const int rl  = tid >> 2;          // local row 0..63
    const int base = blockIdx.x * ROWS_PB;

    // ---- Stage W via cp.async : group 0 (3072 float4 / 256 thr = 12 each) ----
    {
        const float4* Wsrc = reinterpret_cast<const float4*>(W);
        #pragma unroll
        for (int i = 0; i < 12; i++) {
            int g4 = i * BLOCK + tid;
            cp_async16(W_s + g4 * 4, reinterpret_cast<const float*>(Wsrc + g4));
        }
        asm volatile("cp.async.commit_group;");
    }
    // ---- Prefetch x chunks 0,1 : groups 1,2 ----
    stage_x(x, x_s, base, 0, tid);
    stage_x(x, x_s + XS_FLOATS, base, 1, tid);

    unsigned long long acc[8];         // acc[i]: lo=col 2i, hi=col 2i+1 (partial: k==q mod 4)
    #pragma unroll
    for (int i = 0; i < 8; i++) acc[i] = 0ull;

    for (int ch = 0; ch < NCHUNK; ch++) {
        if (ch < NCHUNK - 1) asm volatile("cp.async.wait_group 1;");
        else                 asm volatile("cp.async.wait_group 0;");
        __syncthreads();

        const float* xr = x_s + (ch & 1) * XS_FLOATS + rl * LDX + q;
        const float* wc = W_s + ch * (KB * NF) + q * NF;

        #pragma unroll
        for (int i = 0; i < 8; i++) {            // k = ch*32 + 4*i + q
            unsigned long long xs = splat(xr[4 * i]);
            const ulonglong2* wp =
                reinterpret_cast<const ulonglong2*>(wc + 4 * i * NF);
            ulonglong2 w01 = wp[0];
            ulonglong2 w23 = wp[1];
            ulonglong2 w45 = wp[2];
            ulonglong2 w67 = wp[3];
            ffma2(acc[0], xs, w01.x);
            ffma2(acc[1], xs, w01.y);
            ffma2(acc[2], xs, w23.x);
            ffma2(acc[3], xs, w23.y);
            ffma2(acc[4], xs, w45.x);
            ffma2(acc[5], xs, w45.y);
            ffma2(acc[6], xs, w67.x);
            ffma2(acc[7], xs, w67.y);
        }
        __syncthreads();
        if (ch + 2 < NCHUNK)
            stage_x(x, x_s + (ch & 1) * XS_FLOATS, base, ch + 2, tid);
    }

    // ---- Reduce the 4 k-quarters (lanes q=0..3 of each row group) ----
    float v[16];
    #pragma unroll
    for (int i = 0; i < 8; i++) {
        v[2 * i]     = __uint_as_float((unsigned int)(acc[i] & 0xffffffffull));
        v[2 * i + 1] = __uint_as_float((unsigned int)(acc[i] >> 32));
    }
    #pragma unroll
    for (int c = 0; c < 16; c++) {
        v[c] += __shfl_xor_sync(0xffffffffu, v[c], 1);
        v[c] += __shfl_xor_sync(0xffffffffu, v[c], 2);
    }

    // ---- Epilogue: lane q handles cols 4q..4q+3 (qubits 2q, 2q+1) ----
    const int row = base + rl;
    float o[4];
    #pragma unroll
    for (int j = 0; j < 2; j++) {
        int c0 = 4 * q + 2 * j;
        int qq = 2 * q + j;
        float z0 = v[c0]     + __ldg(&b[c0]);
        float z1 = v[c0 + 1] + __ldg(&b[c0 + 1]);
        float e0 = __expf(2.0f * z0);
        float e1 = __expf(2.0f * z1);
        float t0 = __fdividef(e0 - 1.0f, e0 + 1.0f);
        float t1 = __fdividef(e1 - 1.0f, e1 + 1.0f);
        float theta = t0 + __ldg(&enc[qq * 3 + 0]);
        float phi   = t1 + __ldg(&enc[qq * 3 + 1]);
        float sn, cs;
        __sincosf(0.5f * theta, &sn, &cs);
        o[2 * j]     = cs;
        o[2 * j + 1] = sn * __cosf(phi);
    }
    reinterpret_cast<float4*>(out + (size_t)row * NF)[q] =
        make_float4(o[0], o[1], o[2], o[3]);
}

extern "C" void kernel_launch(void* const* d_in, const int* in_sizes, int n_in,
                              void* d_out, int out_size) {
    const float* x   = (const float*)d_in[0];
    const float* W   = (const float*)d_in[1];
    const float* b   = (const float*)d_in[2];
    const float* enc = (const float*)d_in[3];
    float* out = (float*)d_out;

    cudaFuncSetAttribute(qadapter_kernel,
                         cudaFuncAttributeMaxDynamicSharedMemorySize, SMEM_BYTES);
    qadapter_kernel<<<ROWS_TOTAL / ROWS_PB, BLOCK, SMEM_BYTES>>>(x, W, b, enc, out);
}

// round 6
// speedup vs baseline: 2.5217x; 2.5217x over previous
#include <cuda_runtime.h>
#include <cstdint>

#define ROWS_TOTAL 32768
#define DIM 768
#define NF 16
#define NQ 8

/* ---------------- kernel 1 : half-K GEMM partials ---------------- */
#define BLOCK 256
#define ROWS_PB 256                  /* 8 warps x 32 rows */
#define KHALF 384
#define KB 32
#define LDX 36                       /* conflict-free padding */
#define NCHUNK (KHALF / KB)          /* 12 */
#define WH_FLOATS (KHALF * NF)       /* 6144 floats = 24KB */
#define XS_FLOATS (ROWS_PB * LDX)    /* 9216 */
#define SMEM_BYTES ((WH_FLOATS + 2 * XS_FLOATS) * 4)  /* 98304 B -> 2 blocks/SM */

__device__ float g_part[2][ROWS_TOTAL * NF];   /* 4MB scratch */

__device__ __forceinline__ void ffma2(unsigned long long &d,
                                      unsigned long long a,
                                      unsigned long long b) {
    asm("fma.rn.f32x2 %0, %1, %2, %0;" : "+l"(d) : "l"(a), "l"(b));
}

__device__ __forceinline__ unsigned long long splat(float v) {
    unsigned long long r;
    asm("mov.b64 %0, {%1, %1};" : "=l"(r) : "f"(v));
    return r;
}

__device__ __forceinline__ void cp_async16(float* dst, const float* src) {
    unsigned int d = (unsigned int)__cvta_generic_to_shared(dst);
    asm volatile("cp.async.cg.shared.global [%0], [%1], 16;" :: "r"(d), "l"(src));
}

__device__ __forceinline__ void stage_x(const float* __restrict__ xh,
                                        float* __restrict__ dst,
                                        int ch, int tid) {
    const float* src = xh + ch * KB;
    /* 256 rows * 32 floats = 2048 float4 ; 256 threads -> 8 each */
    #pragma unroll
    for (int i = 0; i < 8; i++) {
        int pos = i * BLOCK + tid;
        int row = pos >> 3, c4 = (pos & 7) << 2;
        cp_async16(dst + row * LDX + c4, src + (size_t)row * DIM + c4);
    }
    asm volatile("cp.async.commit_group;");
}

__global__ __launch_bounds__(BLOCK)
void qadapter_gemm(const float* __restrict__ x,
                   const float* __restrict__ W) {
    extern __shared__ float smem[];
    float* W_s = smem;                 /* 6144 floats, natural row-major */
    float* x_s = smem + WH_FLOATS;     /* 2 x 9216 floats */

    const int tid  = threadIdx.x;
    const int half = blockIdx.x & 1;
    const int base = (blockIdx.x >> 1) * ROWS_PB;
    const float* xh = x + (size_t)base * DIM + half * KHALF;

    /* ---- stage this half's W : group 0 (1536 float4 / 256 thr = 6) ---- */
    {
        const float4* Wsrc =
            reinterpret_cast<const float4*>(W + half * KHALF * NF);
        #pragma unroll
        for (int i = 0; i < 6; i++) {
            int g4 = i * BLOCK + tid;
            cp_async16(W_s + g4 * 4, reinterpret_cast<const float*>(Wsrc + g4));
        }
        asm volatile("cp.async.commit_group;");
    }
    stage_x(xh, x_s, 0, tid);                     /* group 1 */
    stage_x(xh, x_s + XS_FLOATS, 1, tid);         /* group 2 */

    unsigned long long acc[8];
    #pragma unroll
    for (int i = 0; i < 8; i++) acc[i] = 0ull;

    for (int ch = 0; ch < NCHUNK; ch++) {
        if (ch < NCHUNK - 1) asm volatile("cp.async.wait_group 1;");
        else                 asm volatile("cp.async.wait_group 0;");
        __syncthreads();

        const float* xr = x_s + (ch & 1) * XS_FLOATS + tid * LDX;
        const float* wc = W_s + ch * (KB * NF);

        #pragma unroll
        for (int kk = 0; kk < KB; kk += 4) {
            float4 xv = *reinterpret_cast<const float4*>(xr + kk);
            float xk[4] = {xv.x, xv.y, xv.z, xv.w};
            #pragma unroll
            for (int j = 0; j < 4; j++) {
                unsigned long long xs = splat(xk[j]);
                const ulonglong2* wp =
                    reinterpret_cast<const ulonglong2*>(wc + (kk + j) * NF);
                ulonglong2 w01 = wp[0];   /* full-warp broadcast LDS.128 */
                ulonglong2 w23 = wp[1];
                ulonglong2 w45 = wp[2];
                ulonglong2 w67 = wp[3];
                ffma2(acc[0], xs, w01.x);
                ffma2(acc[1], xs, w01.y);
                ffma2(acc[2], xs, w23.x);
                ffma2(acc[3], xs, w23.y);
                ffma2(acc[4], xs, w45.x);
                ffma2(acc[5], xs, w45.y);
                ffma2(acc[6], xs, w67.x);
                ffma2(acc[7], xs, w67.y);
            }
        }
        __syncthreads();
        if (ch + 2 < NCHUNK)
            stage_x(xh, x_s + (ch & 1) * XS_FLOATS, ch + 2, tid);
    }

    /* ---- write fp32 partials ---- */
    float4* dst = reinterpret_cast<float4*>(
        &g_part[half][(size_t)(base + tid) * NF]);
    #pragma unroll
    for (int i = 0; i < 4; i++) {
        float a = __uint_as_float((unsigned int)(acc[2 * i] & 0xffffffffull));
        float bb = __uint_as_float((unsigned int)(acc[2 * i] >> 32));
        float c = __uint_as_float((unsigned int)(acc[2 * i + 1] & 0xffffffffull));
        float d = __uint_as_float((unsigned int)(acc[2 * i + 1] >> 32));
        dst[i] = make_float4(a, bb, c, d);
    }
}

/* ---------------- kernel 2 : combine + tanh + quantum encode ------------- */
__global__ __launch_bounds__(256)
void qadapter_epi(const float* __restrict__ b,
                  const float* __restrict__ enc,
                  float* __restrict__ out) {
    const int row = blockIdx.x * 256 + threadIdx.x;
    const float4* p0 = reinterpret_cast<const float4*>(&g_part[0][(size_t)row * NF]);
    const float4* p1 = reinterpret_cast<const float4*>(&g_part[1][(size_t)row * NF]);

    float s[16];
    #pragma unroll
    for (int i = 0; i < 4; i++) {
        float4 a = p0[i];
        float4 c = p1[i];
        float z0 = a.x + c.x + __ldg(&b[4 * i]);
        float z1 = a.y + c.y + __ldg(&b[4 * i + 1]);
        float z2 = a.z + c.z + __ldg(&b[4 * i + 2]);
        float z3 = a.w + c.w + __ldg(&b[4 * i + 3]);
        float e0 = __expf(2.0f * z0), e1 = __expf(2.0f * z1);
        float e2 = __expf(2.0f * z2), e3 = __expf(2.0f * z3);
        s[4 * i]     = __fdividef(e0 - 1.0f, e0 + 1.0f);
        s[4 * i + 1] = __fdividef(e1 - 1.0f, e1 + 1.0f);
        s[4 * i + 2] = __fdividef(e2 - 1.0f, e2 + 1.0f);
        s[4 * i + 3] = __fdividef(e3 - 1.0f, e3 + 1.0f);
    }
    float o[16];
    #pragma unroll
    for (int q = 0; q < NQ; q++) {
        float theta = s[2 * q]     + __ldg(&enc[q * 3 + 0]);
        float phi   = s[2 * q + 1] + __ldg(&enc[q * 3 + 1]);
        float sn, cs;
        __sincosf(0.5f * theta, &sn, &cs);
        o[2 * q]     = cs;
        o[2 * q + 1] = sn * __cosf(phi);
    }
    float4* op = reinterpret_cast<float4*>(out + (size_t)row * NF);
    #pragma unroll
    for (int i = 0; i < 4; i++)
        op[i] = make_float4(o[4 * i], o[4 * i + 1], o[4 * i + 2], o[4 * i + 3]);
}

extern "C" void kernel_launch(void* const* d_in, const int* in_sizes, int n_in,
                              void* d_out, int out_size) {
    const float* x   = (const float*)d_in[0];
    const float* W   = (const float*)d_in[1];
    const float* b   = (const float*)d_in[2];
    const float* enc = (const float*)d_in[3];
    float* out = (float*)d_out;

    cudaFuncSetAttribute(qadapter_gemm,
                         cudaFuncAttributeMaxDynamicSharedMemorySize, SMEM_BYTES);
    qadapter_gemm<<<(ROWS_TOTAL / ROWS_PB) * 2, BLOCK, SMEM_BYTES>>>(x, W);
    qadapter_epi<<<ROWS_TOTAL / 256, 256>>>(b, enc, out);
}

// round 8
// speedup vs baseline: 3.0526x; 1.2105x over previous
#include <cuda_runtime.h>
#include <cstdint>

#define ROWS_TOTAL 32768
#define DIM 768
#define NF 16
#define NQ 8

/* ---------- kernel 1 : quarter-K GEMM, 4 rows per thread ---------- */
#define BLOCK 128
#define RPT 4                        /* rows per thread */
#define ROWS_PB (BLOCK * RPT)        /* 512 */
#define KQ 192                       /* K quarter */
#define KB 16                        /* k per chunk */
#define LDX 20                       /* row stride in x smem (conflict-free) */
#define NCHUNK (KQ / KB)             /* 12 */
#define WQ_FLOATS (KQ * NF)          /* 3072 floats = 12KB */
#define XS_FLOATS (ROWS_PB * LDX)    /* 10240 */
#define SMEM_BYTES ((WQ_FLOATS + 2 * XS_FLOATS) * 4)  /* 94208 B -> 2 blocks/SM */

__device__ float g_part[4][ROWS_TOTAL * NF];   /* 8MB scratch */

__device__ __forceinline__ void ffma2(unsigned long long &d,
                                      unsigned long long a,
                                      unsigned long long b) {
    asm("fma.rn.f32x2 %0, %1, %2, %0;" : "+l"(d) : "l"(a), "l"(b));
}

__device__ __forceinline__ unsigned long long splat(float v) {
    unsigned long long r;
    asm("mov.b64 %0, {%1, %1};" : "=l"(r) : "f"(v));
    return r;
}

__device__ __forceinline__ void cp_async16(float* dst, const float* src) {
    unsigned int d = (unsigned int)__cvta_generic_to_shared(dst);
    asm volatile("cp.async.cg.shared.global [%0], [%1], 16;" :: "r"(d), "l"(src));
}

/* stage one 512-row x 16-k chunk: 2048 float4, 16 per thread */
__device__ __forceinline__ void stage_x(const float* __restrict__ xq,
                                        float* __restrict__ dst,
                                        int ch, int tid) {
    const float* src = xq + ch * KB;
    #pragma unroll
    for (int i = 0; i < 16; i++) {
        int pos = i * BLOCK + tid;
        int row = pos >> 2, c4 = (pos & 3) << 2;
        cp_async16(dst + row * LDX + c4, src + (size_t)row * DIM + c4);
    }
    asm volatile("cp.async.commit_group;");
}

__global__ __launch_bounds__(BLOCK)
void qadapter_gemm(const float* __restrict__ x,
                   const float* __restrict__ W) {
    extern __shared__ float smem[];
    float* W_s = smem;                 /* 3072 floats */
    float* x_s = smem + WQ_FLOATS;     /* 2 x 10240 floats */

    const int tid     = threadIdx.x;
    const int quarter = blockIdx.x & 3;
    const int base    = (blockIdx.x >> 2) * ROWS_PB;
    const float* xq   = x + (size_t)base * DIM + quarter * KQ;

    /* stage this quarter's W : group 0 (768 float4 / 128 thr = 6 each) */
    {
        const float4* Wsrc =
            reinterpret_cast<const float4*>(W + quarter * KQ * NF);
        #pragma unroll
        for (int i = 0; i < 6; i++) {
            int g4 = i * BLOCK + tid;
            cp_async16(W_s + g4 * 4, reinterpret_cast<const float*>(Wsrc + g4));
        }
        asm volatile("cp.async.commit_group;");
    }
    stage_x(xq, x_s, 0, tid);                 /* group 1 */
    stage_x(xq, x_s + XS_FLOATS, 1, tid);     /* group 2 */

    unsigned long long acc[RPT][8];    /* [row][col-pair] */
    #pragma unroll
    for (int j = 0; j < RPT; j++)
        #pragma unroll
        for (int i = 0; i < 8; i++) acc[j][i] = 0ull;

    for (int ch = 0; ch < NCHUNK; ch++) {
        if (ch < NCHUNK - 1) asm volatile("cp.async.wait_group 1;");
        else                 asm volatile("cp.async.wait_group 0;");
        __syncthreads();

        const float* xb = x_s + (ch & 1) * XS_FLOATS + tid * LDX;
        const float* wc = W_s + ch * (KB * NF);

        #pragma unroll
        for (int kk = 0; kk < KB; kk += 4) {
            float4 xv[RPT];
            #pragma unroll
            for (int j = 0; j < RPT; j++)
                xv[j] = *reinterpret_cast<const float4*>(
                    xb + j * (BLOCK * LDX) + kk);
            const float xe[RPT][4] = {
                {xv[0].x, xv[0].y, xv[0].z, xv[0].w},
                {xv[1].x, xv[1].y, xv[1].z, xv[1].w},
                {xv[2].x, xv[2].y, xv[2].z, xv[2].w},
                {xv[3].x, xv[3].y, xv[3].z, xv[3].w}};
            #pragma unroll
            for (int kj = 0; kj < 4; kj++) {
                const ulonglong2* wp = reinterpret_cast<const ulonglong2*>(
                    wc + (kk + kj) * NF);
                ulonglong2 w01 = wp[0];   /* full-warp broadcast LDS.128 */
                ulonglong2 w23 = wp[1];
                ulonglong2 w45 = wp[2];
                ulonglong2 w67 = wp[3];
                #pragma unroll
                for (int j = 0; j < RPT; j++) {
                    unsigned long long xs = splat(xe[j][kj]);
                    ffma2(acc[j][0], xs, w01.x);
                    ffma2(acc[j][1], xs, w01.y);
                    ffma2(acc[j][2], xs, w23.x);
                    ffma2(acc[j][3], xs, w23.y);
                    ffma2(acc[j][4], xs, w45.x);
                    ffma2(acc[j][5], xs, w45.y);
                    ffma2(acc[j][6], xs, w67.x);
                    ffma2(acc[j][7], xs, w67.y);
                }
            }
        }
        __syncthreads();
        if (ch + 2 < NCHUNK)
            stage_x(xq, x_s + (ch & 1) * XS_FLOATS, ch + 2, tid);
    }

    /* write fp32 partials for 4 rows */
    #pragma unroll
    for (int j = 0; j < RPT; j++) {
        float4* dst = reinterpret_cast<float4*>(
            &g_part[quarter][(size_t)(base + tid + j * BLOCK) * NF]);
        #pragma unroll
        for (int i = 0; i < 4; i++) {
            float a = __uint_as_float((unsigned int)(acc[j][2 * i] & 0xffffffffull));
            float bb = __uint_as_float((unsigned int)(acc[j][2 * i] >> 32));
            float c = __uint_as_float((unsigned int)(acc[j][2 * i + 1] & 0xffffffffull));
            float d = __uint_as_float((unsigned int)(acc[j][2 * i + 1] >> 32));
            dst[i] = make_float4(a, bb, c, d);
        }
    }
}

/* ---------- kernel 2 : combine quarters + tanh + quantum encode ---------- */
__global__ __launch_bounds__(256)
void qadapter_epi(const float* __restrict__ b,
                  const float* __restrict__ enc,
                  float* __restrict__ out) {
    const int row = blockIdx.x * 256 + threadIdx.x;

    float s[16];
    #pragma unroll
    for (int i = 0; i < 4; i++) {
        float4 a0 = reinterpret_cast<const float4*>(&g_part[0][(size_t)row * NF])[i];
        float4 a1 = reinterpret_cast<const float4*>(&g_part[1][(size_t)row * NF])[i];
        float4 a2 = reinterpret_cast<const float4*>(&g_part[2][(size_t)row * NF])[i];
        float4 a3 = reinterpret_cast<const float4*>(&g_part[3][(size_t)row * NF])[i];
        float z0 = (a0.x + a1.x) + (a2.x + a3.x) + __ldg(&b[4 * i]);
        float z1 = (a0.y + a1.y) + (a2.y + a3.y) + __ldg(&b[4 * i + 1]);
        float z2 = (a0.z + a1.z) + (a2.z + a3.z) + __ldg(&b[4 * i + 2]);
        float z3 = (a0.w + a1.w) + (a2.w + a3.w) + __ldg(&b[4 * i + 3]);
        float e0 = __expf(2.0f * z0), e1 = __expf(2.0f * z1);
        float e2 = __expf(2.0f * z2), e3 = __expf(2.0f * z3);
        s[4 * i]     = __fdividef(e0 - 1.0f, e0 + 1.0f);
        s[4 * i + 1] = __fdividef(e1 - 1.0f, e1 + 1.0f);
        s[4 * i + 2] = __fdividef(e2 - 1.0f, e2 + 1.0f);
        s[4 * i + 3] = __fdividef(e3 - 1.0f, e3 + 1.0f);
    }
    float o[16];
    #pragma unroll
    for (int q = 0; q < NQ; q++) {
        float theta = s[2 * q]     + __ldg(&enc[q * 3 + 0]);
        float phi   = s[2 * q + 1] + __ldg(&enc[q * 3 + 1]);
        float sn, cs;
        __sincosf(0.5f * theta, &sn, &cs);
        o[2 * q]     = cs;
        o[2 * q + 1] = sn * __cosf(phi);
    }
    float4* op = reinterpret_cast<float4*>(out + (size_t)row * NF);
    #pragma unroll
    for (int i = 0; i < 4; i++)
        op[i] = make_float4(o[4 * i], o[4 * i + 1], o[4 * i + 2], o[4 * i + 3]);
}

extern "C" void kernel_launch(void* const* d_in, const int* in_sizes, int n_in,
                              void* d_out, int out_size) {
    const float* x   = (const float*)d_in[0];
    const float* W   = (const float*)d_in[1];
    const float* b   = (const float*)d_in[2];
    const float* enc = (const float*)d_in[3];
    float* out = (float*)d_out;

    cudaFuncSetAttribute(qadapter_gemm,
                         cudaFuncAttributeMaxDynamicSharedMemorySize, SMEM_BYTES);
    qadapter_gemm<<<(ROWS_TOTAL / ROWS_PB) * 4, BLOCK, SMEM_BYTES>>>(x, W);
    qadapter_epi<<<ROWS_TOTAL / 256, 256>>>(b, enc, out);
}